// round 1
// baseline (speedup 1.0000x reference)
#include <cuda_runtime.h>
#include <math.h>

// Problem shape (fixed): x[8,512,768] -> M=4096, E=768. Two NT GEMMs 4096x768x768
// with a fused per-8-column "quantum" epilogue after GEMM1:
//   c_i = cos(proj_i + theta_i);  ez[w>=1] = c0..cw (prefix product); ez[0] = c1..c7
#define MM 4096
#define NN 768
#define KK 768

// Scratch for the intermediate (expz) matrix. Allocation-free rule -> device global.
__device__ float g_mid[(size_t)MM * NN];

// EPI == 1: A = x, epilogue = bias + theta -> cos -> prefix products, write g_mid
// EPI == 0: A = g_mid, epilogue = bias, write C (d_out)
template <int EPI>
__global__ __launch_bounds__(256, 2)
void gemm_nt_kernel(const float* __restrict__ A,
                    const float* __restrict__ B,
                    const float* __restrict__ bias,
                    const float* __restrict__ theta,
                    float* __restrict__ C)
{
    __shared__ float As[16][128];
    __shared__ float Bs[16][128];

    const int bm = blockIdx.y * 128;
    const int bn = blockIdx.x * 128;
    const int t  = threadIdx.x;
    const int tx = t & 15;   // 16 threads across N, 8 cols each (aligned head groups)
    const int ty = t >> 4;   // 16 threads across M, 8 rows each

    const float* __restrict__ Ap = (EPI == 0) ? (const float*)g_mid : A;

    float acc[8][8];
#pragma unroll
    for (int i = 0; i < 8; i++)
#pragma unroll
        for (int j = 0; j < 8; j++) acc[i][j] = 0.f;

    for (int k0 = 0; k0 < KK; k0 += 16) {
        // Cooperative loads: 2 float4 per thread per operand, transposed into smem.
#pragma unroll
        for (int i = 0; i < 2; i++) {
            int lin = t + i * 256;
            int row = lin >> 2;           // 0..127
            int kv  = (lin & 3) << 2;     // 0,4,8,12
            float4 va = *(const float4*)(Ap + (size_t)(bm + row) * KK + (k0 + kv));
            As[kv + 0][row] = va.x; As[kv + 1][row] = va.y;
            As[kv + 2][row] = va.z; As[kv + 3][row] = va.w;
            float4 vb = *(const float4*)(B + (size_t)(bn + row) * KK + (k0 + kv));
            Bs[kv + 0][row] = vb.x; Bs[kv + 1][row] = vb.y;
            Bs[kv + 2][row] = vb.z; Bs[kv + 3][row] = vb.w;
        }
        __syncthreads();

#pragma unroll
        for (int k = 0; k < 16; k++) {
            float ar[8], br[8];
#pragma unroll
            for (int i = 0; i < 2; i++) {
                float4 v = *(const float4*)&As[k][ty * 8 + i * 4];
                ar[i * 4 + 0] = v.x; ar[i * 4 + 1] = v.y;
                ar[i * 4 + 2] = v.z; ar[i * 4 + 3] = v.w;
            }
#pragma unroll
            for (int j = 0; j < 2; j++) {
                float4 v = *(const float4*)&Bs[k][tx * 8 + j * 4];
                br[j * 4 + 0] = v.x; br[j * 4 + 1] = v.y;
                br[j * 4 + 2] = v.z; br[j * 4 + 3] = v.w;
            }
#pragma unroll
            for (int i = 0; i < 8; i++)
#pragma unroll
                for (int j = 0; j < 8; j++)
                    acc[i][j] = fmaf(ar[i], br[j], acc[i][j]);
        }
        __syncthreads();
    }

    const int gn = bn + tx * 8;  // multiple of 8 -> this thread owns whole head groups
    float bvals[8];
#pragma unroll
    for (int j = 0; j < 8; j++) bvals[j] = bias[gn + j];

    if (EPI == 1) {
        float th[8];
#pragma unroll
        for (int j = 0; j < 8; j++) th[j] = theta[j];
#pragma unroll
        for (int i = 0; i < 8; i++) {
            float c[8];
#pragma unroll
            for (int j = 0; j < 8; j++)
                c[j] = cosf(acc[i][j] + bvals[j] + th[j]);
            float o[8];
            float p = c[0];
#pragma unroll
            for (int w = 1; w < 8; w++) { p *= c[w]; o[w] = p; }
            float q = c[1];
#pragma unroll
            for (int w = 2; w < 8; w++) q *= c[w];
            o[0] = q;
            float* dst = g_mid + (size_t)(bm + ty * 8 + i) * NN + gn;
            *(float4*)(dst + 0) = make_float4(o[0], o[1], o[2], o[3]);
            *(float4*)(dst + 4) = make_float4(o[4], o[5], o[6], o[7]);
        }
    } else {
#pragma unroll
        for (int i = 0; i < 8; i++) {
            float* dst = C + (size_t)(bm + ty * 8 + i) * NN + gn;
            *(float4*)(dst + 0) = make_float4(acc[i][0] + bvals[0], acc[i][1] + bvals[1],
                                              acc[i][2] + bvals[2], acc[i][3] + bvals[3]);
            *(float4*)(dst + 4) = make_float4(acc[i][4] + bvals[4], acc[i][5] + bvals[5],
                                              acc[i][6] + bvals[6], acc[i][7] + bvals[7]);
        }
    }
}

extern "C" void kernel_launch(void* const* d_in, const int* in_sizes, int n_in,
                              void* d_out, int out_size)
{
    const float* x      = (const float*)d_in[0];  // [4096, 768]
    const float* W_proj = (const float*)d_in[1];  // [768, 768]
    const float* b_proj = (const float*)d_in[2];  // [768]
    const float* theta  = (const float*)d_in[3];  // [8]
    const float* W_comb = (const float*)d_in[4];  // [768, 768]
    const float* b_comb = (const float*)d_in[5];  // [768]
    float* out = (float*)d_out;                   // [4096, 768]

    dim3 grid(NN / 128, MM / 128);   // (6, 32)
    dim3 block(256);

    // GEMM1 + fused quantum epilogue -> g_mid
    gemm_nt_kernel<1><<<grid, block>>>(x, W_proj, b_proj, theta, nullptr);
    // GEMM2 (+bias) -> out
    gemm_nt_kernel<0><<<grid, block>>>(nullptr, W_comb, b_comb, nullptr, out);
}

// round 3
// speedup vs baseline: 2.2535x; 2.2535x over previous
#include <cuda_runtime.h>
#include <cuda_bf16.h>
#include <cstdint>
#include <math.h>

// M=4096, E=768. Two NT GEMMs 4096x768x768 via mma.sync bf16 (3-term hi/lo
// split for fp32-like accuracy), fused quantum epilogue after GEMM1.
#define MM 4096
#define NNE 768
#define KK 768
#define NCH 24            // K chunks of 32
#define ROWB 80           // smem bytes per row (32 bf16 padded to 40 elems)
#define TILE_SM 10240     // 128 * 80
#define BUF_SM 40960      // Ah, Al, Bh, Bl tiles
#define SMEM_BYTES 81920  // double buffered
#define EPI_STRIDE 132    // floats per row in epilogue staging

// ---------------- device globals (allocation-free scratch) ----------------
__device__ __align__(16) __nv_bfloat16 g_xh[(size_t)MM * KK], g_xl[(size_t)MM * KK];
__device__ __align__(16) __nv_bfloat16 g_wph[(size_t)KK * NNE], g_wpl[(size_t)KK * NNE];
__device__ __align__(16) __nv_bfloat16 g_wch[(size_t)KK * NNE], g_wcl[(size_t)KK * NNE];
__device__ __align__(16) __nv_bfloat16 g_mh[(size_t)MM * NNE], g_ml[(size_t)MM * NNE];

// ---------------- helpers ----------------
__device__ __forceinline__ uint32_t pk2(__nv_bfloat16 a, __nv_bfloat16 b) {
    __nv_bfloat162 v = __halves2bfloat162(a, b);
    return *(uint32_t*)&v;
}
__device__ __forceinline__ void ldsm4(uint32_t& r0, uint32_t& r1, uint32_t& r2, uint32_t& r3,
                                      uint32_t addr) {
    asm volatile("ldmatrix.sync.aligned.m8n8.x4.shared.b16 {%0,%1,%2,%3}, [%4];"
                 : "=r"(r0), "=r"(r1), "=r"(r2), "=r"(r3) : "r"(addr));
}
__device__ __forceinline__ void mma16816(float* d, const uint32_t* a, const uint32_t* b) {
    asm volatile("mma.sync.aligned.m16n8k16.row.col.f32.bf16.bf16.f32 "
                 "{%0,%1,%2,%3}, {%4,%5,%6,%7}, {%8,%9}, {%0,%1,%2,%3};"
                 : "+f"(d[0]), "+f"(d[1]), "+f"(d[2]), "+f"(d[3])
                 : "r"(a[0]), "r"(a[1]), "r"(a[2]), "r"(a[3]), "r"(b[0]), "r"(b[1]));
}
__device__ __forceinline__ void cpa16(uint32_t dst, const void* src) {
    asm volatile("cp.async.cg.shared.global [%0], [%1], 16;" :: "r"(dst), "l"(src));
}

// ---------------- prep: fp32 -> bf16 hi/lo ----------------
template <int WHICH>  // 0: x, 1: W_proj, 2: W_comb
__global__ void split_kernel(const float* __restrict__ src, int n4) {
    int i = blockIdx.x * blockDim.x + threadIdx.x;
    if (i >= n4) return;
    __nv_bfloat16* hi = (WHICH == 0) ? g_xh : (WHICH == 1) ? g_wph : g_wch;
    __nv_bfloat16* lo = (WHICH == 0) ? g_xl : (WHICH == 1) ? g_wpl : g_wcl;
    float4 v = ((const float4*)src)[i];
    float f[4] = {v.x, v.y, v.z, v.w};
    __nv_bfloat16 h[4], l[4];
#pragma unroll
    for (int j = 0; j < 4; j++) {
        h[j] = __float2bfloat16(f[j]);
        l[j] = __float2bfloat16(f[j] - __bfloat162float(h[j]));
    }
    *(uint2*)(hi + (size_t)i * 4) = make_uint2(pk2(h[0], h[1]), pk2(h[2], h[3]));
    *(uint2*)(lo + (size_t)i * 4) = make_uint2(pk2(l[0], l[1]), pk2(l[2], l[3]));
}

// ---------------- main GEMM, PASS 1: quantum epilogue, PASS 2: bias epilogue ----
template <int PASS>
__global__ __launch_bounds__(256)
void qgemm_kernel(const float* __restrict__ bias, const float* __restrict__ theta,
                  float* __restrict__ out)
{
    extern __shared__ __align__(16) char smem[];
    const uint32_t sb = (uint32_t)__cvta_generic_to_shared(smem);
    const int t = threadIdx.x, lane = t & 31, wid = t >> 5;
    const int warp_m = wid >> 2, warp_n = wid & 3;   // 2 x 4 warps, warp tile 64x32
    const int bm = blockIdx.y * 128, bn = blockIdx.x * 128;

    const __nv_bfloat16* Ah = (PASS == 1) ? g_xh : g_mh;
    const __nv_bfloat16* Al = (PASS == 1) ? g_xl : g_ml;
    const __nv_bfloat16* Bhp = (PASS == 1) ? g_wph : g_wch;
    const __nv_bfloat16* Blp = (PASS == 1) ? g_wpl : g_wcl;

    // per-thread ldmatrix base offsets (within a buffer)
    const uint32_t aOff = (uint32_t)((warp_m * 64 + (lane & 15)) * ROWB + (lane >> 4) * 16);
    const uint32_t bRow = (uint32_t)(warp_n * 32 + (lane & 7) + ((lane >> 4) & 1) * 8);
    const uint32_t bOff = 2u * TILE_SM + bRow * ROWB + ((lane >> 3) & 1) * 16;

    float acc[4][4][4];
#pragma unroll
    for (int mt = 0; mt < 4; mt++)
#pragma unroll
        for (int nt = 0; nt < 4; nt++)
#pragma unroll
            for (int r = 0; r < 4; r++) acc[mt][nt][r] = 0.f;

    // issue loads for one chunk into buffer b
    auto issue = [&](int c, int b) {
#pragma unroll
        for (int i = 0; i < 8; i++) {
            int tile = i >> 1;                    // 0:Ah 1:Al 2:Bh 3:Bl
            int rem = t + (i & 1) * 256;          // 0..511
            int row = rem >> 2, q = rem & 3;
            const __nv_bfloat16* src;
            if (tile == 0)      src = Ah + (size_t)(bm + row) * KK;
            else if (tile == 1) src = Al + (size_t)(bm + row) * KK;
            else if (tile == 2) src = Bhp + (size_t)(bn + row) * KK;
            else                src = Blp + (size_t)(bn + row) * KK;
            src += c * 32 + q * 8;
            uint32_t dst = sb + b * BUF_SM + tile * TILE_SM + row * ROWB + q * 16;
            cpa16(dst, src);
        }
        asm volatile("cp.async.commit_group;" ::: "memory");
    };

    issue(0, 0);
    for (int c = 0; c < NCH; ++c) {
        if (c + 1 < NCH) {
            issue(c + 1, (c + 1) & 1);
            asm volatile("cp.async.wait_group 1;" ::: "memory");
        } else {
            asm volatile("cp.async.wait_group 0;" ::: "memory");
        }
        __syncthreads();

        const uint32_t bufB = sb + (c & 1) * BUF_SM;
        const uint32_t aH = bufB + aOff;
        const uint32_t aL = aH + TILE_SM;
        const uint32_t bH = bufB + bOff;
        const uint32_t bL = bH + TILE_SM;
#pragma unroll
        for (int ks = 0; ks < 2; ks++) {
            const uint32_t ko = ks * 32;
            uint32_t bh[4][2], bl[4][2], af[4][4];
#pragma unroll
            for (int np = 0; np < 2; np++) {
                ldsm4(bh[2 * np][0], bh[2 * np][1], bh[2 * np + 1][0], bh[2 * np + 1][1],
                      bH + np * (16 * ROWB) + ko);
                ldsm4(bl[2 * np][0], bl[2 * np][1], bl[2 * np + 1][0], bl[2 * np + 1][1],
                      bL + np * (16 * ROWB) + ko);
            }
#pragma unroll
            for (int mt = 0; mt < 4; mt++)
                ldsm4(af[mt][0], af[mt][1], af[mt][2], af[mt][3], aH + mt * (16 * ROWB) + ko);
#pragma unroll
            for (int mt = 0; mt < 4; mt++)
#pragma unroll
                for (int nt = 0; nt < 4; nt++) mma16816(acc[mt][nt], af[mt], bh[nt]);
#pragma unroll
            for (int mt = 0; mt < 4; mt++)
#pragma unroll
                for (int nt = 0; nt < 4; nt++) mma16816(acc[mt][nt], af[mt], bl[nt]);
#pragma unroll
            for (int mt = 0; mt < 4; mt++)
                ldsm4(af[mt][0], af[mt][1], af[mt][2], af[mt][3], aL + mt * (16 * ROWB) + ko);
#pragma unroll
            for (int mt = 0; mt < 4; mt++)
#pragma unroll
                for (int nt = 0; nt < 4; nt++) mma16816(acc[mt][nt], af[mt], bh[nt]);
        }
        __syncthreads();
    }

    // ---- stage accumulators to smem for head-aligned epilogue ----
    float* smf = (float*)smem;
#pragma unroll
    for (int mt = 0; mt < 4; mt++)
#pragma unroll
        for (int nt = 0; nt < 4; nt++) {
            int r0 = warp_m * 64 + mt * 16 + (lane >> 2);
            int col = warp_n * 32 + nt * 8 + (lane & 3) * 2;
            smf[r0 * EPI_STRIDE + col]           = acc[mt][nt][0];
            smf[r0 * EPI_STRIDE + col + 1]       = acc[mt][nt][1];
            smf[(r0 + 8) * EPI_STRIDE + col]     = acc[mt][nt][2];
            smf[(r0 + 8) * EPI_STRIDE + col + 1] = acc[mt][nt][3];
        }
    __syncthreads();

    if (PASS == 1) {
        float th[8];
#pragma unroll
        for (int j = 0; j < 8; j++) th[j] = theta[j];
#pragma unroll
        for (int i = 0; i < 8; i++) {
            int gid = t + i * 256;       // 2048 head-groups: 128 rows x 16 heads
            int row = gid >> 4, head = gid & 15;
            const float* src = smf + row * EPI_STRIDE + head * 8;
            float cc[8];
#pragma unroll
            for (int j = 0; j < 8; j++)
                cc[j] = cosf(src[j] + bias[bn + head * 8 + j] + th[j]);
            float o[8];
            float p = cc[0];
#pragma unroll
            for (int w = 1; w < 8; w++) { p *= cc[w]; o[w] = p; }
            float q = cc[1];
#pragma unroll
            for (int w = 2; w < 8; w++) q *= cc[w];
            o[0] = q;
            __nv_bfloat16 h[8], l[8];
#pragma unroll
            for (int j = 0; j < 8; j++) {
                h[j] = __float2bfloat16(o[j]);
                l[j] = __float2bfloat16(o[j] - __bfloat162float(h[j]));
            }
            size_t doff = (size_t)(bm + row) * NNE + bn + head * 8;
            *(uint4*)(g_mh + doff) = make_uint4(pk2(h[0], h[1]), pk2(h[2], h[3]),
                                                pk2(h[4], h[5]), pk2(h[6], h[7]));
            *(uint4*)(g_ml + doff) = make_uint4(pk2(l[0], l[1]), pk2(l[2], l[3]),
                                                pk2(l[4], l[5]), pk2(l[6], l[7]));
        }
    } else {
#pragma unroll
        for (int i = 0; i < 16; i++) {
            int idx = t + i * 256;       // 4096 float4s: 128 rows x 32
            int row = idx >> 5, c4 = idx & 31;
            const float* src = smf + row * EPI_STRIDE + c4 * 4;
            float4 v;
            v.x = src[0] + bias[bn + c4 * 4 + 0];
            v.y = src[1] + bias[bn + c4 * 4 + 1];
            v.z = src[2] + bias[bn + c4 * 4 + 2];
            v.w = src[3] + bias[bn + c4 * 4 + 3];
            *(float4*)(out + (size_t)(bm + row) * NNE + bn + c4 * 4) = v;
        }
    }
}

// ---------------- launch ----------------
extern "C" void kernel_launch(void* const* d_in, const int* in_sizes, int n_in,
                              void* d_out, int out_size)
{
    const float* x      = (const float*)d_in[0];  // [4096, 768]
    const float* W_proj = (const float*)d_in[1];  // [768, 768]
    const float* b_proj = (const float*)d_in[2];  // [768]
    const float* theta  = (const float*)d_in[3];  // [8]
    const float* W_comb = (const float*)d_in[4];  // [768, 768]
    const float* b_comb = (const float*)d_in[5];  // [768]
    float* out = (float*)d_out;                   // [4096, 768]

    cudaFuncSetAttribute(qgemm_kernel<1>, cudaFuncAttributeMaxDynamicSharedMemorySize, SMEM_BYTES);
    cudaFuncSetAttribute(qgemm_kernel<2>, cudaFuncAttributeMaxDynamicSharedMemorySize, SMEM_BYTES);

    int n4 = MM * KK / 4;
    split_kernel<0><<<(n4 + 255) / 256, 256>>>(x, n4);
    int w4 = KK * NNE / 4;
    split_kernel<1><<<(w4 + 255) / 256, 256>>>(W_proj, w4);
    split_kernel<2><<<(w4 + 255) / 256, 256>>>(W_comb, w4);

    dim3 grid(NNE / 128, MM / 128);  // (6, 32)
    qgemm_kernel<1><<<grid, 256, SMEM_BYTES>>>(b_proj, theta, nullptr);
    qgemm_kernel<2><<<grid, 256, SMEM_BYTES>>>(b_comb, nullptr, out);
}

// round 4
// speedup vs baseline: 2.3497x; 1.0427x over previous
#include <cuda_runtime.h>
#include <cuda_bf16.h>
#include <cstdint>
#include <math.h>

// M=4096, E=768. Two NT GEMMs 4096x768x768 via mma.sync bf16 (3-term hi/lo
// split for fp32-like accuracy), fused quantum epilogue after GEMM1.
// R4: 2 CTAs/SM co-residency (one full wave, cross-CTA latency hiding).
#define MM 4096
#define NNE 768
#define KK 768
#define NCH 24            // K chunks of 32
#define ROWB 80           // smem bytes per row (32 bf16 padded to 40 elems)
#define TILE_SM 10240     // 128 * 80
#define BUF_SM 40960      // Ah, Al, Bh, Bl tiles
#define SMEM_BYTES 81920  // double buffered
#define EPI_STRIDE 132    // floats per row in epilogue staging

// ---------------- device globals (allocation-free scratch) ----------------
__device__ __align__(16) __nv_bfloat16 g_xh[(size_t)MM * KK], g_xl[(size_t)MM * KK];
__device__ __align__(16) __nv_bfloat16 g_wph[(size_t)KK * NNE], g_wpl[(size_t)KK * NNE];
__device__ __align__(16) __nv_bfloat16 g_wch[(size_t)KK * NNE], g_wcl[(size_t)KK * NNE];
__device__ __align__(16) __nv_bfloat16 g_mh[(size_t)MM * NNE], g_ml[(size_t)MM * NNE];

// ---------------- helpers ----------------
__device__ __forceinline__ uint32_t pk2(__nv_bfloat16 a, __nv_bfloat16 b) {
    __nv_bfloat162 v = __halves2bfloat162(a, b);
    return *(uint32_t*)&v;
}
__device__ __forceinline__ void ldsm4(uint32_t& r0, uint32_t& r1, uint32_t& r2, uint32_t& r3,
                                      uint32_t addr) {
    asm volatile("ldmatrix.sync.aligned.m8n8.x4.shared.b16 {%0,%1,%2,%3}, [%4];"
                 : "=r"(r0), "=r"(r1), "=r"(r2), "=r"(r3) : "r"(addr));
}
__device__ __forceinline__ void mma16816(float* d, const uint32_t* a, const uint32_t* b) {
    asm volatile("mma.sync.aligned.m16n8k16.row.col.f32.bf16.bf16.f32 "
                 "{%0,%1,%2,%3}, {%4,%5,%6,%7}, {%8,%9}, {%0,%1,%2,%3};"
                 : "+f"(d[0]), "+f"(d[1]), "+f"(d[2]), "+f"(d[3])
                 : "r"(a[0]), "r"(a[1]), "r"(a[2]), "r"(a[3]), "r"(b[0]), "r"(b[1]));
}
__device__ __forceinline__ void cpa16(uint32_t dst, const void* src) {
    asm volatile("cp.async.cg.shared.global [%0], [%1], 16;" :: "r"(dst), "l"(src));
}

// ---------------- prep: fp32 -> bf16 hi/lo ----------------
template <int WHICH>  // 0: x, 1: W_proj, 2: W_comb
__global__ void split_kernel(const float* __restrict__ src, int n4) {
    int i = blockIdx.x * blockDim.x + threadIdx.x;
    if (i >= n4) return;
    __nv_bfloat16* hi = (WHICH == 0) ? g_xh : (WHICH == 1) ? g_wph : g_wch;
    __nv_bfloat16* lo = (WHICH == 0) ? g_xl : (WHICH == 1) ? g_wpl : g_wcl;
    float4 v = ((const float4*)src)[i];
    float f[4] = {v.x, v.y, v.z, v.w};
    __nv_bfloat16 h[4], l[4];
#pragma unroll
    for (int j = 0; j < 4; j++) {
        h[j] = __float2bfloat16(f[j]);
        l[j] = __float2bfloat16(f[j] - __bfloat162float(h[j]));
    }
    *(uint2*)(hi + (size_t)i * 4) = make_uint2(pk2(h[0], h[1]), pk2(h[2], h[3]));
    *(uint2*)(lo + (size_t)i * 4) = make_uint2(pk2(l[0], l[1]), pk2(l[2], l[3]));
}

// ---------------- main GEMM, PASS 1: quantum epilogue, PASS 2: bias epilogue ----
template <int PASS>
__global__ __launch_bounds__(256, 2)
void qgemm_kernel(const float* __restrict__ bias, const float* __restrict__ theta,
                  float* __restrict__ out)
{
    extern __shared__ __align__(16) char smem[];
    const uint32_t sb = (uint32_t)__cvta_generic_to_shared(smem);
    const int t = threadIdx.x, lane = t & 31, wid = t >> 5;
    const int warp_m = wid >> 2, warp_n = wid & 3;   // 2 x 4 warps, warp tile 64x32
    const int bm = blockIdx.y * 128, bn = blockIdx.x * 128;

    const __nv_bfloat16* Ah = (PASS == 1) ? g_xh : g_mh;
    const __nv_bfloat16* Al = (PASS == 1) ? g_xl : g_ml;
    const __nv_bfloat16* Bhp = (PASS == 1) ? g_wph : g_wch;
    const __nv_bfloat16* Blp = (PASS == 1) ? g_wpl : g_wcl;

    // per-thread cp.async source pointers (hoisted; only k-offset varies)
    const int ldRow = t >> 2, ldQ = (t & 3);
    const __nv_bfloat16* srcA_h = Ah + (size_t)(bm + ldRow) * KK + ldQ * 8;
    const __nv_bfloat16* srcA_h2 = Ah + (size_t)(bm + ldRow + 64) * KK + ldQ * 8;
    const __nv_bfloat16* srcA_l = Al + (size_t)(bm + ldRow) * KK + ldQ * 8;
    const __nv_bfloat16* srcA_l2 = Al + (size_t)(bm + ldRow + 64) * KK + ldQ * 8;
    const __nv_bfloat16* srcB_h = Bhp + (size_t)(bn + ldRow) * KK + ldQ * 8;
    const __nv_bfloat16* srcB_h2 = Bhp + (size_t)(bn + ldRow + 64) * KK + ldQ * 8;
    const __nv_bfloat16* srcB_l = Blp + (size_t)(bn + ldRow) * KK + ldQ * 8;
    const __nv_bfloat16* srcB_l2 = Blp + (size_t)(bn + ldRow + 64) * KK + ldQ * 8;
    const uint32_t dBase = sb + ldRow * ROWB + ldQ * 16;

    // per-thread ldmatrix base offsets (within a buffer)
    const uint32_t aOff = (uint32_t)((warp_m * 64 + (lane & 15)) * ROWB + (lane >> 4) * 16);
    const uint32_t bRow = (uint32_t)(warp_n * 32 + (lane & 7) + ((lane >> 4) & 1) * 8);
    const uint32_t bOff = 2u * TILE_SM + bRow * ROWB + ((lane >> 3) & 1) * 16;

    float acc[4][4][4];
#pragma unroll
    for (int mt = 0; mt < 4; mt++)
#pragma unroll
        for (int nt = 0; nt < 4; nt++)
#pragma unroll
            for (int r = 0; r < 4; r++) acc[mt][nt][r] = 0.f;

    auto issue = [&](int c, int b) {
        const int ko = c * 32;
        const uint32_t d0 = dBase + b * BUF_SM;
        cpa16(d0,                               srcA_h + ko);
        cpa16(d0 + 64 * ROWB,                   srcA_h2 + ko);
        cpa16(d0 + TILE_SM,                     srcA_l + ko);
        cpa16(d0 + TILE_SM + 64 * ROWB,         srcA_l2 + ko);
        cpa16(d0 + 2 * TILE_SM,                 srcB_h + ko);
        cpa16(d0 + 2 * TILE_SM + 64 * ROWB,     srcB_h2 + ko);
        cpa16(d0 + 3 * TILE_SM,                 srcB_l + ko);
        cpa16(d0 + 3 * TILE_SM + 64 * ROWB,     srcB_l2 + ko);
        asm volatile("cp.async.commit_group;" ::: "memory");
    };

    issue(0, 0);
    for (int c = 0; c < NCH; ++c) {
        if (c + 1 < NCH) {
            issue(c + 1, (c + 1) & 1);
            asm volatile("cp.async.wait_group 1;" ::: "memory");
        } else {
            asm volatile("cp.async.wait_group 0;" ::: "memory");
        }
        __syncthreads();

        const uint32_t bufB = sb + (c & 1) * BUF_SM;
        const uint32_t aH = bufB + aOff;
        const uint32_t aL = aH + TILE_SM;
        const uint32_t bH = bufB + bOff;
        const uint32_t bL = bH + TILE_SM;
#pragma unroll
        for (int ks = 0; ks < 2; ks++) {
            const uint32_t ko = ks * 32;
            uint32_t bh[4][2], bl[4][2], af[4][4];
#pragma unroll
            for (int np = 0; np < 2; np++) {
                ldsm4(bh[2 * np][0], bh[2 * np][1], bh[2 * np + 1][0], bh[2 * np + 1][1],
                      bH + np * (16 * ROWB) + ko);
                ldsm4(bl[2 * np][0], bl[2 * np][1], bl[2 * np + 1][0], bl[2 * np + 1][1],
                      bL + np * (16 * ROWB) + ko);
            }
#pragma unroll
            for (int mt = 0; mt < 4; mt++)
                ldsm4(af[mt][0], af[mt][1], af[mt][2], af[mt][3], aH + mt * (16 * ROWB) + ko);
#pragma unroll
            for (int mt = 0; mt < 4; mt++)
#pragma unroll
                for (int nt = 0; nt < 4; nt++) mma16816(acc[mt][nt], af[mt], bh[nt]);
#pragma unroll
            for (int mt = 0; mt < 4; mt++)
#pragma unroll
                for (int nt = 0; nt < 4; nt++) mma16816(acc[mt][nt], af[mt], bl[nt]);
#pragma unroll
            for (int mt = 0; mt < 4; mt++)
                ldsm4(af[mt][0], af[mt][1], af[mt][2], af[mt][3], aL + mt * (16 * ROWB) + ko);
#pragma unroll
            for (int mt = 0; mt < 4; mt++)
#pragma unroll
                for (int nt = 0; nt < 4; nt++) mma16816(acc[mt][nt], af[mt], bh[nt]);
        }
        __syncthreads();
    }

    // ---- stage accumulators to smem for head-aligned epilogue ----
    float* smf = (float*)smem;
#pragma unroll
    for (int mt = 0; mt < 4; mt++)
#pragma unroll
        for (int nt = 0; nt < 4; nt++) {
            int r0 = warp_m * 64 + mt * 16 + (lane >> 2);
            int col = warp_n * 32 + nt * 8 + (lane & 3) * 2;
            smf[r0 * EPI_STRIDE + col]           = acc[mt][nt][0];
            smf[r0 * EPI_STRIDE + col + 1]       = acc[mt][nt][1];
            smf[(r0 + 8) * EPI_STRIDE + col]     = acc[mt][nt][2];
            smf[(r0 + 8) * EPI_STRIDE + col + 1] = acc[mt][nt][3];
        }
    __syncthreads();

    if (PASS == 1) {
        float th[8];
#pragma unroll
        for (int j = 0; j < 8; j++) th[j] = theta[j];
#pragma unroll
        for (int i = 0; i < 8; i++) {
            int gid = t + i * 256;       // 2048 head-groups: 128 rows x 16 heads
            int row = gid >> 4, head = gid & 15;
            const float* src = smf + row * EPI_STRIDE + head * 8;
            float cc[8];
#pragma unroll
            for (int j = 0; j < 8; j++)
                cc[j] = cosf(src[j] + bias[bn + head * 8 + j] + th[j]);
            float o[8];
            float p = cc[0];
#pragma unroll
            for (int w = 1; w < 8; w++) { p *= cc[w]; o[w] = p; }
            float q = cc[1];
#pragma unroll
            for (int w = 2; w < 8; w++) q *= cc[w];
            o[0] = q;
            __nv_bfloat16 h[8], l[8];
#pragma unroll
            for (int j = 0; j < 8; j++) {
                h[j] = __float2bfloat16(o[j]);
                l[j] = __float2bfloat16(o[j] - __bfloat162float(h[j]));
            }
            size_t doff = (size_t)(bm + row) * NNE + bn + head * 8;
            *(uint4*)(g_mh + doff) = make_uint4(pk2(h[0], h[1]), pk2(h[2], h[3]),
                                                pk2(h[4], h[5]), pk2(h[6], h[7]));
            *(uint4*)(g_ml + doff) = make_uint4(pk2(l[0], l[1]), pk2(l[2], l[3]),
                                                pk2(l[4], l[5]), pk2(l[6], l[7]));
        }
    } else {
#pragma unroll
        for (int i = 0; i < 16; i++) {
            int idx = t + i * 256;       // 4096 float4s: 128 rows x 32
            int row = idx >> 5, c4 = idx & 31;
            const float* src = smf + row * EPI_STRIDE + c4 * 4;
            float4 v;
            v.x = src[0] + bias[bn + c4 * 4 + 0];
            v.y = src[1] + bias[bn + c4 * 4 + 1];
            v.z = src[2] + bias[bn + c4 * 4 + 2];
            v.w = src[3] + bias[bn + c4 * 4 + 3];
            *(float4*)(out + (size_t)(bm + row) * NNE + bn + c4 * 4) = v;
        }
    }
}

// ---------------- launch ----------------
extern "C" void kernel_launch(void* const* d_in, const int* in_sizes, int n_in,
                              void* d_out, int out_size)
{
    const float* x      = (const float*)d_in[0];  // [4096, 768]
    const float* W_proj = (const float*)d_in[1];  // [768, 768]
    const float* b_proj = (const float*)d_in[2];  // [768]
    const float* theta  = (const float*)d_in[3];  // [8]
    const float* W_comb = (const float*)d_in[4];  // [768, 768]
    const float* b_comb = (const float*)d_in[5];  // [768]
    float* out = (float*)d_out;                   // [4096, 768]

    cudaFuncSetAttribute(qgemm_kernel<1>, cudaFuncAttributeMaxDynamicSharedMemorySize, SMEM_BYTES);
    cudaFuncSetAttribute(qgemm_kernel<2>, cudaFuncAttributeMaxDynamicSharedMemorySize, SMEM_BYTES);

    int n4 = MM * KK / 4;
    split_kernel<0><<<(n4 + 255) / 256, 256>>>(x, n4);
    int w4 = KK * NNE / 4;
    split_kernel<1><<<(w4 + 255) / 256, 256>>>(W_proj, w4);
    split_kernel<2><<<(w4 + 255) / 256, 256>>>(W_comb, w4);

    dim3 grid(NNE / 128, MM / 128);  // (6, 32)
    qgemm_kernel<1><<<grid, 256, SMEM_BYTES>>>(b_proj, theta, nullptr);
    qgemm_kernel<2><<<grid, 256, SMEM_BYTES>>>(b_comb, nullptr, out);
}

// round 5
// speedup vs baseline: 2.8116x; 1.1966x over previous
#include <cuda_runtime.h>
#include <cuda_bf16.h>
#include <cstdint>
#include <math.h>

// M=4096, E=768. Two NT GEMMs 4096x768x768 via mma.sync bf16 (3-term hi/lo
// split), fused quantum epilogue after GEMM1.
// R5: 128x64 tiles -> 384 CTAs, 3 CTAs/SM, single-sync 2-stage pipeline.
#define MM 4096
#define NNE 768
#define KK 768
#define NCH 24            // K chunks of 32
#define ROWB 80           // smem bytes per row (32 bf16 padded)
#define A_SM (128 * ROWB) // 10240
#define B_SM (64 * ROWB)  // 5120
#define BUF_SM (2 * A_SM + 2 * B_SM)  // 30720: Ah, Al, Bh, Bl
#define SMEM_BYTES (2 * BUF_SM)       // 61440 double buffered
#define EPI_STRIDE 68     // floats per row in epilogue staging (128*68*4 <= smem)

// ---------------- device globals (allocation-free scratch) ----------------
__device__ __align__(16) __nv_bfloat16 g_xh[(size_t)MM * KK], g_xl[(size_t)MM * KK];
__device__ __align__(16) __nv_bfloat16 g_wph[(size_t)KK * NNE], g_wpl[(size_t)KK * NNE];
__device__ __align__(16) __nv_bfloat16 g_wch[(size_t)KK * NNE], g_wcl[(size_t)KK * NNE];
__device__ __align__(16) __nv_bfloat16 g_mh[(size_t)MM * NNE], g_ml[(size_t)MM * NNE];

// ---------------- helpers ----------------
__device__ __forceinline__ uint32_t pk2(__nv_bfloat16 a, __nv_bfloat16 b) {
    __nv_bfloat162 v = __halves2bfloat162(a, b);
    return *(uint32_t*)&v;
}
__device__ __forceinline__ void ldsm4(uint32_t& r0, uint32_t& r1, uint32_t& r2, uint32_t& r3,
                                      uint32_t addr) {
    asm volatile("ldmatrix.sync.aligned.m8n8.x4.shared.b16 {%0,%1,%2,%3}, [%4];"
                 : "=r"(r0), "=r"(r1), "=r"(r2), "=r"(r3) : "r"(addr));
}
__device__ __forceinline__ void mma16816(float* d, const uint32_t* a, const uint32_t* b) {
    asm volatile("mma.sync.aligned.m16n8k16.row.col.f32.bf16.bf16.f32 "
                 "{%0,%1,%2,%3}, {%4,%5,%6,%7}, {%8,%9}, {%0,%1,%2,%3};"
                 : "+f"(d[0]), "+f"(d[1]), "+f"(d[2]), "+f"(d[3])
                 : "r"(a[0]), "r"(a[1]), "r"(a[2]), "r"(a[3]), "r"(b[0]), "r"(b[1]));
}
__device__ __forceinline__ void cpa16(uint32_t dst, const void* src) {
    asm volatile("cp.async.cg.shared.global [%0], [%1], 16;" :: "r"(dst), "l"(src));
}

// ---------------- prep: fp32 -> bf16 hi/lo ----------------
template <int WHICH>
__global__ void split_kernel(const float* __restrict__ src, int n4) {
    int i = blockIdx.x * blockDim.x + threadIdx.x;
    if (i >= n4) return;
    __nv_bfloat16* hi = (WHICH == 0) ? g_xh : (WHICH == 1) ? g_wph : g_wch;
    __nv_bfloat16* lo = (WHICH == 0) ? g_xl : (WHICH == 1) ? g_wpl : g_wcl;
    float4 v = ((const float4*)src)[i];
    float f[4] = {v.x, v.y, v.z, v.w};
    __nv_bfloat16 h[4], l[4];
#pragma unroll
    for (int j = 0; j < 4; j++) {
        h[j] = __float2bfloat16(f[j]);
        l[j] = __float2bfloat16(f[j] - __bfloat162float(h[j]));
    }
    *(uint2*)(hi + (size_t)i * 4) = make_uint2(pk2(h[0], h[1]), pk2(h[2], h[3]));
    *(uint2*)(lo + (size_t)i * 4) = make_uint2(pk2(l[0], l[1]), pk2(l[2], l[3]));
}

// ---------------- main GEMM, PASS 1: quantum epilogue, PASS 2: bias epilogue ----
template <int PASS>
__global__ __launch_bounds__(256, 3)
void qgemm_kernel(const float* __restrict__ bias, const float* __restrict__ theta,
                  float* __restrict__ out)
{
    extern __shared__ __align__(16) char smem[];
    const uint32_t sb = (uint32_t)__cvta_generic_to_shared(smem);
    const int t = threadIdx.x, lane = t & 31, wid = t >> 5;
    const int warp_m = wid >> 1, warp_n = wid & 1;   // 4 x 2 warps, warp tile 32x32
    const int bm = blockIdx.y * 128, bn = blockIdx.x * 64;

    const __nv_bfloat16* Ah = (PASS == 1) ? g_xh : g_mh;
    const __nv_bfloat16* Al = (PASS == 1) ? g_xl : g_ml;
    const __nv_bfloat16* Bhp = (PASS == 1) ? g_wph : g_wch;
    const __nv_bfloat16* Blp = (PASS == 1) ? g_wpl : g_wcl;

    // cp.async: 6 16B loads per thread per chunk
    const int ldRow = t >> 2, ldQ = t & 3;
    const __nv_bfloat16* srcA_h  = Ah + (size_t)(bm + ldRow) * KK + ldQ * 8;
    const __nv_bfloat16* srcA_h2 = Ah + (size_t)(bm + ldRow + 64) * KK + ldQ * 8;
    const __nv_bfloat16* srcA_l  = Al + (size_t)(bm + ldRow) * KK + ldQ * 8;
    const __nv_bfloat16* srcA_l2 = Al + (size_t)(bm + ldRow + 64) * KK + ldQ * 8;
    const __nv_bfloat16* srcB_h  = Bhp + (size_t)(bn + ldRow) * KK + ldQ * 8;
    const __nv_bfloat16* srcB_l  = Blp + (size_t)(bn + ldRow) * KK + ldQ * 8;
    const uint32_t dBase = sb + ldRow * ROWB + ldQ * 16;

    // ldmatrix base offsets
    const uint32_t aOff = (uint32_t)((warp_m * 32 + (lane & 15)) * ROWB + (lane >> 4) * 16);
    const uint32_t bRow = (uint32_t)(warp_n * 32 + (lane & 7) + ((lane >> 4) & 1) * 8);
    const uint32_t bOff = 2u * A_SM + bRow * ROWB + ((lane >> 3) & 1) * 16;

    float acc[2][4][4];
#pragma unroll
    for (int mt = 0; mt < 2; mt++)
#pragma unroll
        for (int nt = 0; nt < 4; nt++)
#pragma unroll
            for (int r = 0; r < 4; r++) acc[mt][nt][r] = 0.f;

    auto issue = [&](int c, int b) {
        const int ko = c * 32;
        const uint32_t d0 = dBase + b * BUF_SM;
        cpa16(d0,                        srcA_h + ko);
        cpa16(d0 + 64 * ROWB,            srcA_h2 + ko);
        cpa16(d0 + A_SM,                 srcA_l + ko);
        cpa16(d0 + A_SM + 64 * ROWB,     srcA_l2 + ko);
        cpa16(d0 + 2 * A_SM,             srcB_h + ko);
        cpa16(d0 + 2 * A_SM + B_SM,      srcB_l + ko);
        asm volatile("cp.async.commit_group;" ::: "memory");
    };

    issue(0, 0);
    for (int c = 0; c < NCH; ++c) {
        asm volatile("cp.async.wait_group 0;" ::: "memory");
        __syncthreads();   // all warps done with compute(c-1) -> buffer (c+1)&1 free
        if (c + 1 < NCH) issue(c + 1, (c + 1) & 1);

        const uint32_t bufB = sb + (c & 1) * BUF_SM;
#pragma unroll
        for (int ks = 0; ks < 2; ks++) {
            const uint32_t ko = ks * 32;
            uint32_t bh[4][2], bl[4][2], af[2][4];
#pragma unroll
            for (int np = 0; np < 2; np++) {
                ldsm4(bh[2 * np][0], bh[2 * np][1], bh[2 * np + 1][0], bh[2 * np + 1][1],
                      bufB + bOff + np * (16 * ROWB) + ko);
                ldsm4(bl[2 * np][0], bl[2 * np][1], bl[2 * np + 1][0], bl[2 * np + 1][1],
                      bufB + bOff + B_SM + np * (16 * ROWB) + ko);
            }
#pragma unroll
            for (int mt = 0; mt < 2; mt++)
                ldsm4(af[mt][0], af[mt][1], af[mt][2], af[mt][3],
                      bufB + aOff + mt * (16 * ROWB) + ko);
#pragma unroll
            for (int mt = 0; mt < 2; mt++)
#pragma unroll
                for (int nt = 0; nt < 4; nt++) mma16816(acc[mt][nt], af[mt], bh[nt]);
#pragma unroll
            for (int mt = 0; mt < 2; mt++)
#pragma unroll
                for (int nt = 0; nt < 4; nt++) mma16816(acc[mt][nt], af[mt], bl[nt]);
#pragma unroll
            for (int mt = 0; mt < 2; mt++)
                ldsm4(af[mt][0], af[mt][1], af[mt][2], af[mt][3],
                      bufB + A_SM + aOff + mt * (16 * ROWB) + ko);
#pragma unroll
            for (int mt = 0; mt < 2; mt++)
#pragma unroll
                for (int nt = 0; nt < 4; nt++) mma16816(acc[mt][nt], af[mt], bh[nt]);
        }
        __syncthreads();   // compute(c) done before next iter's issue overwrites c&1
    }

    // ---- stage accumulators to smem for head-aligned epilogue ----
    float* smf = (float*)smem;
#pragma unroll
    for (int mt = 0; mt < 2; mt++)
#pragma unroll
        for (int nt = 0; nt < 4; nt++) {
            int r0 = warp_m * 32 + mt * 16 + (lane >> 2);
            int col = warp_n * 32 + nt * 8 + (lane & 3) * 2;
            smf[r0 * EPI_STRIDE + col]           = acc[mt][nt][0];
            smf[r0 * EPI_STRIDE + col + 1]       = acc[mt][nt][1];
            smf[(r0 + 8) * EPI_STRIDE + col]     = acc[mt][nt][2];
            smf[(r0 + 8) * EPI_STRIDE + col + 1] = acc[mt][nt][3];
        }
    __syncthreads();

    if (PASS == 1) {
        float th[8];
#pragma unroll
        for (int j = 0; j < 8; j++) th[j] = theta[j];
#pragma unroll
        for (int i = 0; i < 4; i++) {
            int gid = t + i * 256;       // 1024 head-groups: 128 rows x 8 heads
            int row = gid >> 3, head = gid & 7;
            const float* src = smf + row * EPI_STRIDE + head * 8;
            float cc[8];
#pragma unroll
            for (int j = 0; j < 8; j++)
                cc[j] = cosf(src[j] + bias[bn + head * 8 + j] + th[j]);
            float o[8];
            float p = cc[0];
#pragma unroll
            for (int w = 1; w < 8; w++) { p *= cc[w]; o[w] = p; }
            float q = cc[1];
#pragma unroll
            for (int w = 2; w < 8; w++) q *= cc[w];
            o[0] = q;
            __nv_bfloat16 h[8], l[8];
#pragma unroll
            for (int j = 0; j < 8; j++) {
                h[j] = __float2bfloat16(o[j]);
                l[j] = __float2bfloat16(o[j] - __bfloat162float(h[j]));
            }
            size_t doff = (size_t)(bm + row) * NNE + bn + head * 8;
            *(uint4*)(g_mh + doff) = make_uint4(pk2(h[0], h[1]), pk2(h[2], h[3]),
                                                pk2(h[4], h[5]), pk2(h[6], h[7]));
            *(uint4*)(g_ml + doff) = make_uint4(pk2(l[0], l[1]), pk2(l[2], l[3]),
                                                pk2(l[4], l[5]), pk2(l[6], l[7]));
        }
    } else {
#pragma unroll
        for (int i = 0; i < 8; i++) {
            int idx = t + i * 256;       // 2048 float4s: 128 rows x 16
            int row = idx >> 4, c4 = idx & 15;
            const float* src = smf + row * EPI_STRIDE + c4 * 4;
            float4 v;
            v.x = src[0] + bias[bn + c4 * 4 + 0];
            v.y = src[1] + bias[bn + c4 * 4 + 1];
            v.z = src[2] + bias[bn + c4 * 4 + 2];
            v.w = src[3] + bias[bn + c4 * 4 + 3];
            *(float4*)(out + (size_t)(bm + row) * NNE + bn + c4 * 4) = v;
        }
    }
}

// ---------------- launch ----------------
extern "C" void kernel_launch(void* const* d_in, const int* in_sizes, int n_in,
                              void* d_out, int out_size)
{
    const float* x      = (const float*)d_in[0];  // [4096, 768]
    const float* W_proj = (const float*)d_in[1];  // [768, 768]
    const float* b_proj = (const float*)d_in[2];  // [768]
    const float* theta  = (const float*)d_in[3];  // [8]
    const float* W_comb = (const float*)d_in[4];  // [768, 768]
    const float* b_comb = (const float*)d_in[5];  // [768]
    float* out = (float*)d_out;                   // [4096, 768]

    cudaFuncSetAttribute(qgemm_kernel<1>, cudaFuncAttributeMaxDynamicSharedMemorySize, SMEM_BYTES);
    cudaFuncSetAttribute(qgemm_kernel<2>, cudaFuncAttributeMaxDynamicSharedMemorySize, SMEM_BYTES);

    int n4 = MM * KK / 4;
    split_kernel<0><<<(n4 + 255) / 256, 256>>>(x, n4);
    int w4 = KK * NNE / 4;
    split_kernel<1><<<(w4 + 255) / 256, 256>>>(W_proj, w4);
    split_kernel<2><<<(w4 + 255) / 256, 256>>>(W_comb, w4);

    dim3 grid(NNE / 64, MM / 128);  // (12, 32) = 384 CTAs
    qgemm_kernel<1><<<grid, 256, SMEM_BYTES>>>(b_proj, theta, nullptr);
    qgemm_kernel<2><<<grid, 256, SMEM_BYTES>>>(b_comb, nullptr, out);
}

// round 6
// speedup vs baseline: 3.2593x; 1.1592x over previous
#include <cuda_runtime.h>
#include <cuda_bf16.h>
#include <cstdint>
#include <math.h>

// M=4096, E=768. Two NT GEMMs 4096x768x768 via mma.sync bf16 (3-term hi/lo
// split), fused quantum epilogue after GEMM1.
// R6: unpadded 64B rows + XOR swizzle, 3-stage depth-2 pipeline, 1 bar/chunk,
//     3 CTAs/SM.
#define MM 4096
#define NNE 768
#define KK 768
#define NCH 24            // K chunks of 32
#define ROWB 64           // smem bytes per row (32 bf16, swizzled not padded)
#define A_SM (128 * ROWB) // 8192
#define B_SM (64 * ROWB)  // 4096
#define BUF_SM (2 * A_SM + 2 * B_SM)  // 24576: Ah, Al, Bh, Bl
#define NSTAGE 3
#define SMEM_BYTES (NSTAGE * BUF_SM)  // 73728
#define EPI_STRIDE 68     // floats per row in epilogue staging

// ---------------- device globals (allocation-free scratch) ----------------
__device__ __align__(16) __nv_bfloat16 g_xh[(size_t)MM * KK], g_xl[(size_t)MM * KK];
__device__ __align__(16) __nv_bfloat16 g_wph[(size_t)KK * NNE], g_wpl[(size_t)KK * NNE];
__device__ __align__(16) __nv_bfloat16 g_wch[(size_t)KK * NNE], g_wcl[(size_t)KK * NNE];
__device__ __align__(16) __nv_bfloat16 g_mh[(size_t)MM * NNE], g_ml[(size_t)MM * NNE];

// ---------------- helpers ----------------
__device__ __forceinline__ uint32_t pk2(__nv_bfloat16 a, __nv_bfloat16 b) {
    __nv_bfloat162 v = __halves2bfloat162(a, b);
    return *(uint32_t*)&v;
}
__device__ __forceinline__ void ldsm4(uint32_t& r0, uint32_t& r1, uint32_t& r2, uint32_t& r3,
                                      uint32_t addr) {
    asm volatile("ldmatrix.sync.aligned.m8n8.x4.shared.b16 {%0,%1,%2,%3}, [%4];"
                 : "=r"(r0), "=r"(r1), "=r"(r2), "=r"(r3) : "r"(addr));
}
__device__ __forceinline__ void mma16816(float* d, const uint32_t* a, const uint32_t* b) {
    asm volatile("mma.sync.aligned.m16n8k16.row.col.f32.bf16.bf16.f32 "
                 "{%0,%1,%2,%3}, {%4,%5,%6,%7}, {%8,%9}, {%0,%1,%2,%3};"
                 : "+f"(d[0]), "+f"(d[1]), "+f"(d[2]), "+f"(d[3])
                 : "r"(a[0]), "r"(a[1]), "r"(a[2]), "r"(a[3]), "r"(b[0]), "r"(b[1]));
}
__device__ __forceinline__ void cpa16(uint32_t dst, const void* src) {
    asm volatile("cp.async.cg.shared.global [%0], [%1], 16;" :: "r"(dst), "l"(src));
}

// ---------------- prep: fp32 -> bf16 hi/lo ----------------
template <int WHICH>
__global__ void split_kernel(const float* __restrict__ src, int n4) {
    int i = blockIdx.x * blockDim.x + threadIdx.x;
    if (i >= n4) return;
    __nv_bfloat16* hi = (WHICH == 0) ? g_xh : (WHICH == 1) ? g_wph : g_wch;
    __nv_bfloat16* lo = (WHICH == 0) ? g_xl : (WHICH == 1) ? g_wpl : g_wcl;
    float4 v = ((const float4*)src)[i];
    float f[4] = {v.x, v.y, v.z, v.w};
    __nv_bfloat16 h[4], l[4];
#pragma unroll
    for (int j = 0; j < 4; j++) {
        h[j] = __float2bfloat16(f[j]);
        l[j] = __float2bfloat16(f[j] - __bfloat162float(h[j]));
    }
    *(uint2*)(hi + (size_t)i * 4) = make_uint2(pk2(h[0], h[1]), pk2(h[2], h[3]));
    *(uint2*)(lo + (size_t)i * 4) = make_uint2(pk2(l[0], l[1]), pk2(l[2], l[3]));
}

// ---------------- main GEMM, PASS 1: quantum epilogue, PASS 2: bias epilogue ----
template <int PASS>
__global__ __launch_bounds__(256, 3)
void qgemm_kernel(const float* __restrict__ bias, const float* __restrict__ theta,
                  float* __restrict__ out)
{
    extern __shared__ __align__(16) char smem[];
    const uint32_t sb = (uint32_t)__cvta_generic_to_shared(smem);
    const int t = threadIdx.x, lane = t & 31, wid = t >> 5;
    const int warp_m = wid >> 1, warp_n = wid & 1;   // 4 x 2 warps, warp tile 32x32
    const int bm = blockIdx.y * 128, bn = blockIdx.x * 64;

    const __nv_bfloat16* Ah = (PASS == 1) ? g_xh : g_mh;
    const __nv_bfloat16* Al = (PASS == 1) ? g_xl : g_ml;
    const __nv_bfloat16* Bhp = (PASS == 1) ? g_wph : g_wch;
    const __nv_bfloat16* Blp = (PASS == 1) ? g_wpl : g_wcl;

    // cp.async: 6 16B loads per thread per chunk, swizzled destination
    const int ldRow = t >> 2, ldQ = t & 3;
    const __nv_bfloat16* srcA_h  = Ah + (size_t)(bm + ldRow) * KK + ldQ * 8;
    const __nv_bfloat16* srcA_h2 = Ah + (size_t)(bm + ldRow + 64) * KK + ldQ * 8;
    const __nv_bfloat16* srcA_l  = Al + (size_t)(bm + ldRow) * KK + ldQ * 8;
    const __nv_bfloat16* srcA_l2 = Al + (size_t)(bm + ldRow + 64) * KK + ldQ * 8;
    const __nv_bfloat16* srcB_h  = Bhp + (size_t)(bn + ldRow) * KK + ldQ * 8;
    const __nv_bfloat16* srcB_l  = Blp + (size_t)(bn + ldRow) * KK + ldQ * 8;
    const uint32_t dBase = sb + ldRow * ROWB + 16u * (ldQ ^ ((ldRow >> 1) & 3));

    // ldmatrix swizzled addressing components
    const int aRow = warp_m * 32 + (lane & 15);           // +mt*16 preserves swizzle
    const int aC   = lane >> 4;                            // 0/1
    const int aSw  = (aRow >> 1) & 3;
    const uint32_t aBase = (uint32_t)(aRow * ROWB);
    const uint32_t aK0 = 16u * ((0 + aC) ^ aSw);
    const uint32_t aK1 = 16u * ((2 + aC) ^ aSw);
    const int bR  = warp_n * 32 + (lane & 7) + ((lane >> 4) & 1) * 8;  // +np*16 ok
    const int bC  = (lane >> 3) & 1;
    const int bSw = (bR >> 1) & 3;
    const uint32_t bBase = (uint32_t)(2 * A_SM + bR * ROWB);
    const uint32_t bK0 = 16u * ((0 + bC) ^ bSw);
    const uint32_t bK1 = 16u * ((2 + bC) ^ bSw);

    float acc[2][4][4];
#pragma unroll
    for (int mt = 0; mt < 2; mt++)
#pragma unroll
        for (int nt = 0; nt < 4; nt++)
#pragma unroll
            for (int r = 0; r < 4; r++) acc[mt][nt][r] = 0.f;

    auto issue = [&](int c, int b) {
        const int ko = c * 32;
        const uint32_t d0 = dBase + b * BUF_SM;
        cpa16(d0,                        srcA_h + ko);
        cpa16(d0 + 64 * ROWB,            srcA_h2 + ko);
        cpa16(d0 + A_SM,                 srcA_l + ko);
        cpa16(d0 + A_SM + 64 * ROWB,     srcA_l2 + ko);
        cpa16(d0 + 2 * A_SM,             srcB_h + ko);
        cpa16(d0 + 2 * A_SM + B_SM,      srcB_l + ko);
        asm volatile("cp.async.commit_group;" ::: "memory");
    };

    issue(0, 0);
    issue(1, 1);
    int buf = 0;
    for (int c = 0; c < NCH; ++c) {
        asm volatile("cp.async.wait_group 1;" ::: "memory");  // chunk c landed
        __syncthreads();            // all warps done compute(c-1) -> buf (c+2)%3 free
        if (c + 2 < NCH) issue(c + 2, (buf + 2 >= NSTAGE) ? buf + 2 - NSTAGE : buf + 2);

        const uint32_t bufB = sb + buf * BUF_SM;
#pragma unroll
        for (int ks = 0; ks < 2; ks++) {
            const uint32_t aKo = ks ? aK1 : aK0;
            const uint32_t bKo = ks ? bK1 : bK0;
            uint32_t bh[4][2], bl[4][2], af[2][4];
#pragma unroll
            for (int np = 0; np < 2; np++) {
                ldsm4(bh[2 * np][0], bh[2 * np][1], bh[2 * np + 1][0], bh[2 * np + 1][1],
                      bufB + bBase + np * (16 * ROWB) + bKo);
                ldsm4(bl[2 * np][0], bl[2 * np][1], bl[2 * np + 1][0], bl[2 * np + 1][1],
                      bufB + bBase + B_SM + np * (16 * ROWB) + bKo);
            }
#pragma unroll
            for (int mt = 0; mt < 2; mt++)
                ldsm4(af[mt][0], af[mt][1], af[mt][2], af[mt][3],
                      bufB + aBase + mt * (16 * ROWB) + aKo);
#pragma unroll
            for (int mt = 0; mt < 2; mt++)
#pragma unroll
                for (int nt = 0; nt < 4; nt++) mma16816(acc[mt][nt], af[mt], bh[nt]);
#pragma unroll
            for (int mt = 0; mt < 2; mt++)
#pragma unroll
                for (int nt = 0; nt < 4; nt++) mma16816(acc[mt][nt], af[mt], bl[nt]);
#pragma unroll
            for (int mt = 0; mt < 2; mt++)
                ldsm4(af[mt][0], af[mt][1], af[mt][2], af[mt][3],
                      bufB + A_SM + aBase + mt * (16 * ROWB) + aKo);
#pragma unroll
            for (int mt = 0; mt < 2; mt++)
#pragma unroll
                for (int nt = 0; nt < 4; nt++) mma16816(acc[mt][nt], af[mt], bh[nt]);
        }
        buf = (buf + 1 >= NSTAGE) ? 0 : buf + 1;
    }
    // Last chunk (23) lives in buffer 2; staging below writes bytes [0, 34816)
    // = buffers 0/1 only, and every warp passed the iter-23 barrier after
    // finishing chunk 22 -> no extra sync needed before staging.

    // ---- stage accumulators to smem for head-aligned epilogue ----
    float* smf = (float*)smem;
#pragma unroll
    for (int mt = 0; mt < 2; mt++)
#pragma unroll
        for (int nt = 0; nt < 4; nt++) {
            int r0 = warp_m * 32 + mt * 16 + (lane >> 2);
            int col = warp_n * 32 + nt * 8 + (lane & 3) * 2;
            smf[r0 * EPI_STRIDE + col]           = acc[mt][nt][0];
            smf[r0 * EPI_STRIDE + col + 1]       = acc[mt][nt][1];
            smf[(r0 + 8) * EPI_STRIDE + col]     = acc[mt][nt][2];
            smf[(r0 + 8) * EPI_STRIDE + col + 1] = acc[mt][nt][3];
        }
    __syncthreads();

    if (PASS == 1) {
        float th[8];
#pragma unroll
        for (int j = 0; j < 8; j++) th[j] = theta[j];
#pragma unroll
        for (int i = 0; i < 4; i++) {
            int gid = t + i * 256;       // 1024 head-groups: 128 rows x 8 heads
            int row = gid >> 3, head = gid & 7;
            const float* src = smf + row * EPI_STRIDE + head * 8;
            float cc[8];
#pragma unroll
            for (int j = 0; j < 8; j++)
                cc[j] = cosf(src[j] + bias[bn + head * 8 + j] + th[j]);
            float o[8];
            float p = cc[0];
#pragma unroll
            for (int w = 1; w < 8; w++) { p *= cc[w]; o[w] = p; }
            float q = cc[1];
#pragma unroll
            for (int w = 2; w < 8; w++) q *= cc[w];
            o[0] = q;
            __nv_bfloat16 h[8], l[8];
#pragma unroll
            for (int j = 0; j < 8; j++) {
                h[j] = __float2bfloat16(o[j]);
                l[j] = __float2bfloat16(o[j] - __bfloat162float(h[j]));
            }
            size_t doff = (size_t)(bm + row) * NNE + bn + head * 8;
            *(uint4*)(g_mh + doff) = make_uint4(pk2(h[0], h[1]), pk2(h[2], h[3]),
                                                pk2(h[4], h[5]), pk2(h[6], h[7]));
            *(uint4*)(g_ml + doff) = make_uint4(pk2(l[0], l[1]), pk2(l[2], l[3]),
                                                pk2(l[4], l[5]), pk2(l[6], l[7]));
        }
    } else {
#pragma unroll
        for (int i = 0; i < 8; i++) {
            int idx = t + i * 256;       // 2048 float4s: 128 rows x 16
            int row = idx >> 4, c4 = idx & 15;
            const float* src = smf + row * EPI_STRIDE + c4 * 4;
            float4 v;
            v.x = src[0] + bias[bn + c4 * 4 + 0];
            v.y = src[1] + bias[bn + c4 * 4 + 1];
            v.z = src[2] + bias[bn + c4 * 4 + 2];
            v.w = src[3] + bias[bn + c4 * 4 + 3];
            *(float4*)(out + (size_t)(bm + row) * NNE + bn + c4 * 4) = v;
        }
    }
}

// ---------------- launch ----------------
extern "C" void kernel_launch(void* const* d_in, const int* in_sizes, int n_in,
                              void* d_out, int out_size)
{
    const float* x      = (const float*)d_in[0];  // [4096, 768]
    const float* W_proj = (const float*)d_in[1];  // [768, 768]
    const float* b_proj = (const float*)d_in[2];  // [768]
    const float* theta  = (const float*)d_in[3];  // [8]
    const float* W_comb = (const float*)d_in[4];  // [768, 768]
    const float* b_comb = (const float*)d_in[5];  // [768]
    float* out = (float*)d_out;                   // [4096, 768]

    cudaFuncSetAttribute(qgemm_kernel<1>, cudaFuncAttributeMaxDynamicSharedMemorySize, SMEM_BYTES);
    cudaFuncSetAttribute(qgemm_kernel<2>, cudaFuncAttributeMaxDynamicSharedMemorySize, SMEM_BYTES);

    int n4 = MM * KK / 4;
    split_kernel<0><<<(n4 + 255) / 256, 256>>>(x, n4);
    int w4 = KK * NNE / 4;
    split_kernel<1><<<(w4 + 255) / 256, 256>>>(W_proj, w4);
    split_kernel<2><<<(w4 + 255) / 256, 256>>>(W_comb, w4);

    dim3 grid(NNE / 64, MM / 128);  // (12, 32) = 384 CTAs
    qgemm_kernel<1><<<grid, 256, SMEM_BYTES>>>(b_proj, theta, nullptr);
    qgemm_kernel<2><<<grid, 256, SMEM_BYTES>>>(b_comb, nullptr, out);
}

// round 8
// speedup vs baseline: 4.3502x; 1.3347x over previous
#include <cuda_runtime.h>
#include <cuda_bf16.h>
#include <cuda_fp16.h>
#include <cstdint>
#include <math.h>

// M=4096, E=768. GEMM1 (x@Wp^T) in bf16 3-term (accuracy-critical, feeds the
// nonlinear quantum head), fused cos/prefix-product epilogue -> fp16 mid.
// GEMM2 (mid@Wc^T) in single-product fp16 (linear, terminal; ~4e-4 rel err).
#define MM 4096
#define NNE 768
#define KK 768

// ---- GEMM1 config (R6 proven) ----
#define NCH1 24
#define ROWB 64
#define A_SM (128 * ROWB)
#define B_SM (64 * ROWB)
#define BUF_SM (2 * A_SM + 2 * B_SM)   // 24576
#define NSTAGE 3
#define SMEM1 (NSTAGE * BUF_SM)        // 73728
// ---- GEMM2 config (fp16 single, K-chunk 64) ----
#define NCH2 12
#define ROWB2 128
#define A_SM2 (128 * ROWB2)            // 16384
#define B_SM2 (64 * ROWB2)             // 8192
#define BUF2 (A_SM2 + B_SM2)           // 24576
#define SMEM2 (3 * BUF2)               // 73728
#define EPI_STRIDE 68

// ---------------- device globals ----------------
__device__ __align__(16) __nv_bfloat16 g_xh[(size_t)MM * KK], g_xl[(size_t)MM * KK];
__device__ __align__(16) __nv_bfloat16 g_wph[(size_t)KK * NNE], g_wpl[(size_t)KK * NNE];
__device__ __align__(16) __half g_wc[(size_t)KK * NNE];
__device__ __align__(16) __half g_mid[(size_t)MM * NNE];

// ---------------- helpers ----------------
__device__ __forceinline__ uint32_t pk2(__nv_bfloat16 a, __nv_bfloat16 b) {
    __nv_bfloat162 v = __halves2bfloat162(a, b);
    return *(uint32_t*)&v;
}
__device__ __forceinline__ uint32_t pkh2(__half a, __half b) {
    __half2 v = __halves2half2(a, b);
    return *(uint32_t*)&v;
}
__device__ __forceinline__ void ldsm4(uint32_t& r0, uint32_t& r1, uint32_t& r2, uint32_t& r3,
                                      uint32_t addr) {
    asm volatile("ldmatrix.sync.aligned.m8n8.x4.shared.b16 {%0,%1,%2,%3}, [%4];"
                 : "=r"(r0), "=r"(r1), "=r"(r2), "=r"(r3) : "r"(addr));
}
__device__ __forceinline__ void mma_bf16(float* d, const uint32_t* a, const uint32_t* b) {
    asm volatile("mma.sync.aligned.m16n8k16.row.col.f32.bf16.bf16.f32 "
                 "{%0,%1,%2,%3}, {%4,%5,%6,%7}, {%8,%9}, {%0,%1,%2,%3};"
                 : "+f"(d[0]), "+f"(d[1]), "+f"(d[2]), "+f"(d[3])
                 : "r"(a[0]), "r"(a[1]), "r"(a[2]), "r"(a[3]), "r"(b[0]), "r"(b[1]));
}
__device__ __forceinline__ void mma_f16(float* d, const uint32_t* a, const uint32_t* b) {
    asm volatile("mma.sync.aligned.m16n8k16.row.col.f32.f16.f16.f32 "
                 "{%0,%1,%2,%3}, {%4,%5,%6,%7}, {%8,%9}, {%0,%1,%2,%3};"
                 : "+f"(d[0]), "+f"(d[1]), "+f"(d[2]), "+f"(d[3])
                 : "r"(a[0]), "r"(a[1]), "r"(a[2]), "r"(a[3]), "r"(b[0]), "r"(b[1]));
}
__device__ __forceinline__ void cpa16(uint32_t dst, const void* src) {
    asm volatile("cp.async.cg.shared.global [%0], [%1], 16;" :: "r"(dst), "l"(src));
}

// ---------------- prep ----------------
template <int WHICH>  // 0: x, 1: W_proj  (bf16 hi/lo)
__global__ void split_kernel(const float* __restrict__ src, int n4) {
    int i = blockIdx.x * blockDim.x + threadIdx.x;
    if (i >= n4) return;
    __nv_bfloat16* hi = (WHICH == 0) ? g_xh : g_wph;
    __nv_bfloat16* lo = (WHICH == 0) ? g_xl : g_wpl;
    float4 v = ((const float4*)src)[i];
    float f[4] = {v.x, v.y, v.z, v.w};
    __nv_bfloat16 h[4], l[4];
#pragma unroll
    for (int j = 0; j < 4; j++) {
        h[j] = __float2bfloat16(f[j]);
        l[j] = __float2bfloat16(f[j] - __bfloat162float(h[j]));
    }
    *(uint2*)(hi + (size_t)i * 4) = make_uint2(pk2(h[0], h[1]), pk2(h[2], h[3]));
    *(uint2*)(lo + (size_t)i * 4) = make_uint2(pk2(l[0], l[1]), pk2(l[2], l[3]));
}

__global__ void conv_half_kernel(const float* __restrict__ src, int n4) {
    int i = blockIdx.x * blockDim.x + threadIdx.x;
    if (i >= n4) return;
    float4 v = ((const float4*)src)[i];
    *(uint2*)(g_wc + (size_t)i * 4) =
        make_uint2(pkh2(__float2half_rn(v.x), __float2half_rn(v.y)),
                   pkh2(__float2half_rn(v.z), __float2half_rn(v.w)));
}

// ---------------- GEMM1: bf16 3-term + quantum epilogue -> g_mid (fp16) ----
__global__ __launch_bounds__(256, 3)
void qgemm1_kernel(const float* __restrict__ bias, const float* __restrict__ theta)
{
    extern __shared__ __align__(16) char smem[];
    const uint32_t sb = (uint32_t)__cvta_generic_to_shared(smem);
    const int t = threadIdx.x, lane = t & 31, wid = t >> 5;
    const int warp_m = wid >> 1, warp_n = wid & 1;   // warp tile 32x32
    const int bm = blockIdx.y * 128, bn = blockIdx.x * 64;

    const int ldRow = t >> 2, ldQ = t & 3;
    const __nv_bfloat16* srcA_h  = g_xh + (size_t)(bm + ldRow) * KK + ldQ * 8;
    const __nv_bfloat16* srcA_h2 = g_xh + (size_t)(bm + ldRow + 64) * KK + ldQ * 8;
    const __nv_bfloat16* srcA_l  = g_xl + (size_t)(bm + ldRow) * KK + ldQ * 8;
    const __nv_bfloat16* srcA_l2 = g_xl + (size_t)(bm + ldRow + 64) * KK + ldQ * 8;
    const __nv_bfloat16* srcB_h  = g_wph + (size_t)(bn + ldRow) * KK + ldQ * 8;
    const __nv_bfloat16* srcB_l  = g_wpl + (size_t)(bn + ldRow) * KK + ldQ * 8;
    const uint32_t dBase = sb + ldRow * ROWB + 16u * (ldQ ^ ((ldRow >> 1) & 3));

    const int aRow = warp_m * 32 + (lane & 15);
    const int aC   = lane >> 4;
    const int aSw  = (aRow >> 1) & 3;
    const uint32_t aBase = (uint32_t)(aRow * ROWB);
    const uint32_t aK0 = 16u * ((0 + aC) ^ aSw);
    const uint32_t aK1 = 16u * ((2 + aC) ^ aSw);
    const int bR  = warp_n * 32 + (lane & 7) + ((lane >> 4) & 1) * 8;
    const int bC  = (lane >> 3) & 1;
    const int bSw = (bR >> 1) & 3;
    const uint32_t bBase = (uint32_t)(2 * A_SM + bR * ROWB);
    const uint32_t bK0 = 16u * ((0 + bC) ^ bSw);
    const uint32_t bK1 = 16u * ((2 + bC) ^ bSw);

    float acc[2][4][4];
#pragma unroll
    for (int mt = 0; mt < 2; mt++)
#pragma unroll
        for (int nt = 0; nt < 4; nt++)
#pragma unroll
            for (int r = 0; r < 4; r++) acc[mt][nt][r] = 0.f;

    auto issue = [&](int c, int b) {
        const int ko = c * 32;
        const uint32_t d0 = dBase + b * BUF_SM;
        cpa16(d0,                        srcA_h + ko);
        cpa16(d0 + 64 * ROWB,            srcA_h2 + ko);
        cpa16(d0 + A_SM,                 srcA_l + ko);
        cpa16(d0 + A_SM + 64 * ROWB,     srcA_l2 + ko);
        cpa16(d0 + 2 * A_SM,             srcB_h + ko);
        cpa16(d0 + 2 * A_SM + B_SM,      srcB_l + ko);
        asm volatile("cp.async.commit_group;" ::: "memory");
    };

    issue(0, 0);
    issue(1, 1);
    int buf = 0;
    for (int c = 0; c < NCH1; ++c) {
        asm volatile("cp.async.wait_group 1;" ::: "memory");
        __syncthreads();
        if (c + 2 < NCH1) issue(c + 2, (buf + 2 >= NSTAGE) ? buf + 2 - NSTAGE : buf + 2);

        const uint32_t bufB = sb + buf * BUF_SM;
#pragma unroll
        for (int ks = 0; ks < 2; ks++) {
            const uint32_t aKo = ks ? aK1 : aK0;
            const uint32_t bKo = ks ? bK1 : bK0;
            uint32_t bh[4][2], bl[4][2], af[2][4];
#pragma unroll
            for (int np = 0; np < 2; np++) {
                ldsm4(bh[2 * np][0], bh[2 * np][1], bh[2 * np + 1][0], bh[2 * np + 1][1],
                      bufB + bBase + np * (16 * ROWB) + bKo);
                ldsm4(bl[2 * np][0], bl[2 * np][1], bl[2 * np + 1][0], bl[2 * np + 1][1],
                      bufB + bBase + B_SM + np * (16 * ROWB) + bKo);
            }
#pragma unroll
            for (int mt = 0; mt < 2; mt++)
                ldsm4(af[mt][0], af[mt][1], af[mt][2], af[mt][3],
                      bufB + aBase + mt * (16 * ROWB) + aKo);
#pragma unroll
            for (int mt = 0; mt < 2; mt++)
#pragma unroll
                for (int nt = 0; nt < 4; nt++) mma_bf16(acc[mt][nt], af[mt], bh[nt]);
#pragma unroll
            for (int mt = 0; mt < 2; mt++)
#pragma unroll
                for (int nt = 0; nt < 4; nt++) mma_bf16(acc[mt][nt], af[mt], bl[nt]);
#pragma unroll
            for (int mt = 0; mt < 2; mt++)
                ldsm4(af[mt][0], af[mt][1], af[mt][2], af[mt][3],
                      bufB + A_SM + aBase + mt * (16 * ROWB) + aKo);
#pragma unroll
            for (int mt = 0; mt < 2; mt++)
#pragma unroll
                for (int nt = 0; nt < 4; nt++) mma_bf16(acc[mt][nt], af[mt], bh[nt]);
        }
        buf = (buf + 1 >= NSTAGE) ? 0 : buf + 1;
    }

    // stage accumulators (bytes [0, 34816) = stages 0/1, free per barrier logic)
    float* smf = (float*)smem;
#pragma unroll
    for (int mt = 0; mt < 2; mt++)
#pragma unroll
        for (int nt = 0; nt < 4; nt++) {
            int r0 = warp_m * 32 + mt * 16 + (lane >> 2);
            int col = warp_n * 32 + nt * 8 + (lane & 3) * 2;
            smf[r0 * EPI_STRIDE + col]           = acc[mt][nt][0];
            smf[r0 * EPI_STRIDE + col + 1]       = acc[mt][nt][1];
            smf[(r0 + 8) * EPI_STRIDE + col]     = acc[mt][nt][2];
            smf[(r0 + 8) * EPI_STRIDE + col + 1] = acc[mt][nt][3];
        }
    __syncthreads();

    float th[8];
#pragma unroll
    for (int j = 0; j < 8; j++) th[j] = theta[j];
#pragma unroll
    for (int i = 0; i < 4; i++) {
        int gid = t + i * 256;           // 1024 head-groups: 128 rows x 8 heads
        int row = gid >> 3, head = gid & 7;
        const float* src = smf + row * EPI_STRIDE + head * 8;
        float cc[8];
#pragma unroll
        for (int j = 0; j < 8; j++)
            cc[j] = cosf(src[j] + bias[bn + head * 8 + j] + th[j]);
        float o[8];
        float p = cc[0];
#pragma unroll
        for (int w = 1; w < 8; w++) { p *= cc[w]; o[w] = p; }
        float q = cc[1];
#pragma unroll
        for (int w = 2; w < 8; w++) q *= cc[w];
        o[0] = q;
        __half h[8];
#pragma unroll
        for (int j = 0; j < 8; j++) h[j] = __float2half_rn(o[j]);
        size_t doff = (size_t)(bm + row) * NNE + bn + head * 8;
        *(uint4*)(g_mid + doff) = make_uint4(pkh2(h[0], h[1]), pkh2(h[2], h[3]),
                                             pkh2(h[4], h[5]), pkh2(h[6], h[7]));
    }
}

// ---------------- GEMM2: fp16 single product + bias -> out ----------------
__global__ __launch_bounds__(256, 3)
void qgemm2_kernel(const float* __restrict__ bias, float* __restrict__ out)
{
    extern __shared__ __align__(16) char smem[];
    const uint32_t sb = (uint32_t)__cvta_generic_to_shared(smem);
    const int t = threadIdx.x, lane = t & 31, wid = t >> 5;
    const int warp_m = wid >> 1, warp_n = wid & 1;   // warp tile 32x32
    const int bm = blockIdx.y * 128, bn = blockIdx.x * 64;

    // cp.async: chunk K=64 (128B rows), 6 16B ops per thread per chunk
    const int ldRow = t >> 3, ldSeg = t & 7;         // rows 0..31, seg 0..7
    const __half* srcA0 = g_mid + (size_t)(bm + ldRow) * KK + ldSeg * 8;
    const __half* srcA1 = g_mid + (size_t)(bm + ldRow + 32) * KK + ldSeg * 8;
    const __half* srcA2 = g_mid + (size_t)(bm + ldRow + 64) * KK + ldSeg * 8;
    const __half* srcA3 = g_mid + (size_t)(bm + ldRow + 96) * KK + ldSeg * 8;
    const __half* srcB0 = g_wc + (size_t)(bn + ldRow) * KK + ldSeg * 8;
    const __half* srcB1 = g_wc + (size_t)(bn + ldRow + 32) * KK + ldSeg * 8;
    const uint32_t dBase = sb + ldRow * ROWB2 + 16u * (ldSeg ^ (ldRow & 7));

    // ldmatrix: slot = 2*ks + c, swizzled by (row & 7); +16/+32 row offsets keep (row&7)
    const int aRow = warp_m * 32 + (lane & 15);
    const int aC   = lane >> 4;
    const int aXor = aRow & 7;
    const uint32_t aBase = (uint32_t)(aRow * ROWB2);
    uint32_t aK[4];
#pragma unroll
    for (int ks = 0; ks < 4; ks++) aK[ks] = 16u * ((2 * ks + aC) ^ aXor);
    const int bR  = warp_n * 32 + (lane & 7) + ((lane >> 4) & 1) * 8;
    const int bC  = (lane >> 3) & 1;
    const int bXor = bR & 7;
    const uint32_t bBase = (uint32_t)(A_SM2 + bR * ROWB2);
    uint32_t bK[4];
#pragma unroll
    for (int ks = 0; ks < 4; ks++) bK[ks] = 16u * ((2 * ks + bC) ^ bXor);

    float acc[2][4][4];
#pragma unroll
    for (int mt = 0; mt < 2; mt++)
#pragma unroll
        for (int nt = 0; nt < 4; nt++)
#pragma unroll
            for (int r = 0; r < 4; r++) acc[mt][nt][r] = 0.f;

    auto issue = [&](int c, int b) {
        const int ko = c * 64;
        const uint32_t d0 = dBase + b * BUF2;
        cpa16(d0,                  srcA0 + ko);
        cpa16(d0 + 32 * ROWB2,     srcA1 + ko);
        cpa16(d0 + 64 * ROWB2,     srcA2 + ko);
        cpa16(d0 + 96 * ROWB2,     srcA3 + ko);
        cpa16(d0 + A_SM2,          srcB0 + ko);
        cpa16(d0 + A_SM2 + 32 * ROWB2, srcB1 + ko);
        asm volatile("cp.async.commit_group;" ::: "memory");
    };

    issue(0, 0);
    issue(1, 1);
    int buf = 0;
    for (int c = 0; c < NCH2; ++c) {
        asm volatile("cp.async.wait_group 1;" ::: "memory");
        __syncthreads();
        if (c + 2 < NCH2) issue(c + 2, (buf + 2 >= 3) ? buf - 1 : buf + 2);

        const uint32_t bufB = sb + buf * BUF2;
#pragma unroll
        for (int ks = 0; ks < 4; ks++) {
            uint32_t bh[4][2], af[2][4];
#pragma unroll
            for (int np = 0; np < 2; np++)
                ldsm4(bh[2 * np][0], bh[2 * np][1], bh[2 * np + 1][0], bh[2 * np + 1][1],
                      bufB + bBase + np * (16 * ROWB2) + bK[ks]);
#pragma unroll
            for (int mt = 0; mt < 2; mt++)
                ldsm4(af[mt][0], af[mt][1], af[mt][2], af[mt][3],
                      bufB + aBase + mt * (16 * ROWB2) + aK[ks]);
#pragma unroll
            for (int mt = 0; mt < 2; mt++)
#pragma unroll
                for (int nt = 0; nt < 4; nt++) mma_f16(acc[mt][nt], af[mt], bh[nt]);
        }
        buf = (buf + 1 >= 3) ? 0 : buf + 1;
    }

    // stage + bias epilogue (bytes [0, 34816) are stages 0/1, free)
    float* smf = (float*)smem;
#pragma unroll
    for (int mt = 0; mt < 2; mt++)
#pragma unroll
        for (int nt = 0; nt < 4; nt++) {
            int r0 = warp_m * 32 + mt * 16 + (lane >> 2);
            int col = warp_n * 32 + nt * 8 + (lane & 3) * 2;
            smf[r0 * EPI_STRIDE + col]           = acc[mt][nt][0];
            smf[r0 * EPI_STRIDE + col + 1]       = acc[mt][nt][1];
            smf[(r0 + 8) * EPI_STRIDE + col]     = acc[mt][nt][2];
            smf[(r0 + 8) * EPI_STRIDE + col + 1] = acc[mt][nt][3];
        }
    __syncthreads();

#pragma unroll
    for (int i = 0; i < 8; i++) {
        int idx = t + i * 256;           // 2048 float4s: 128 rows x 16
        int row = idx >> 4, c4 = idx & 15;
        const float* src = smf + row * EPI_STRIDE + c4 * 4;
        float4 v;
        v.x = src[0] + bias[bn + c4 * 4 + 0];
        v.y = src[1] + bias[bn + c4 * 4 + 1];
        v.z = src[2] + bias[bn + c4 * 4 + 2];
        v.w = src[3] + bias[bn + c4 * 4 + 3];
        *(float4*)(out + (size_t)(bm + row) * NNE + bn + c4 * 4) = v;
    }
}

// ---------------- launch ----------------
extern "C" void kernel_launch(void* const* d_in, const int* in_sizes, int n_in,
                              void* d_out, int out_size)
{
    const float* x      = (const float*)d_in[0];
    const float* W_proj = (const float*)d_in[1];
    const float* b_proj = (const float*)d_in[2];
    const float* theta  = (const float*)d_in[3];
    const float* W_comb = (const float*)d_in[4];
    const float* b_comb = (const float*)d_in[5];
    float* out = (float*)d_out;

    cudaFuncSetAttribute(qgemm1_kernel, cudaFuncAttributeMaxDynamicSharedMemorySize, SMEM1);
    cudaFuncSetAttribute(qgemm2_kernel, cudaFuncAttributeMaxDynamicSharedMemorySize, SMEM2);

    int n4 = MM * KK / 4;
    split_kernel<0><<<(n4 + 255) / 256, 256>>>(x, n4);
    int w4 = KK * NNE / 4;
    split_kernel<1><<<(w4 + 255) / 256, 256>>>(W_proj, w4);
    conv_half_kernel<<<(w4 + 255) / 256, 256>>>(W_comb, w4);

    dim3 grid(NNE / 64, MM / 128);  // (12, 32) = 384 CTAs
    qgemm1_kernel<<<grid, 256, SMEM1>>>(b_proj, theta);
    qgemm2_kernel<<<grid, 256, SMEM2>>>(b_comb, out);
}